// round 1
// baseline (speedup 1.0000x reference)
#include <cuda_runtime.h>
#include <cstdint>

#define N_ATOMS  200000
#define N_FEAT   1024
#define H1_DIM   256
#define H2_DIM   256
#define N_STRUCT 2000

#define M_TILE   128
#define NTHREADS 512
#define KC       32     // k-chunk width

#define SA_STRIDE 36    // 32 + 4 pad (floats)
#define SB_STRIDE 36
#define H1_STRIDE 260   // 256 + 4 pad

// shared memory layout (float offsets)
#define OFF_B     0                      // 2*256*36 = 18432
#define OFF_A     (2*256*SB_STRIDE)      // 18432, size 2*128*36 = 9216
#define OFF_H1    OFF_A                  // aliases A (A dead when h1 written), 128*260 = 33280
#define OFF_WPSL  (OFF_A + 128*H1_STRIDE)   // 51712
#define OFF_WOUT  (OFF_WPSL + 1024)         // 52736
#define OFF_SATOM (OFF_WOUT + 256)          // 52992
#define SMEM_FLOATS (OFF_SATOM + 128)       // 53120
#define SMEM_BYTES (SMEM_FLOATS * 4)        // 212480 B

__device__ __forceinline__ uint32_t cvt_tf32(float x) {
    uint32_t r;
    asm("cvt.rna.tf32.f32 %0, %1;" : "=r"(r) : "f"(x));
    return r;
}

__device__ __forceinline__ void mma_tf32(float c[4], const uint32_t a[4], const uint32_t b[2]) {
    asm volatile(
        "mma.sync.aligned.m16n8k8.row.col.f32.tf32.tf32.f32 "
        "{%0,%1,%2,%3}, {%4,%5,%6,%7}, {%8,%9}, {%0,%1,%2,%3};\n"
        : "+f"(c[0]), "+f"(c[1]), "+f"(c[2]), "+f"(c[3])
        : "r"(a[0]), "r"(a[1]), "r"(a[2]), "r"(a[3]), "r"(b[0]), "r"(b[1]));
}

__device__ __forceinline__ void cp_async16(uint32_t saddr, const void* gptr) {
    asm volatile("cp.async.cg.shared.global [%0], [%1], 16;\n" :: "r"(saddr), "l"(gptr));
}
__device__ __forceinline__ void cp_commit() { asm volatile("cp.async.commit_group;\n"); }
__device__ __forceinline__ void cp_wait1()  { asm volatile("cp.async.wait_group 1;\n"); }
__device__ __forceinline__ void cp_wait0()  { asm volatile("cp.async.wait_group 0;\n"); }

__device__ __forceinline__ float silu(float x) { return x / (1.0f + __expf(-x)); }

__global__ void zero_out_kernel(float* out, int n) {
    int i = blockIdx.x * blockDim.x + threadIdx.x;
    if (i < n) out[i] = 0.0f;
}

__global__ void __launch_bounds__(NTHREADS, 1)
fused_psm_kernel(const float* __restrict__ ps,
                 const int*   __restrict__ numbers,
                 const int*   __restrict__ batch,
                 const float* __restrict__ Wcomp,  // [4]
                 const float* __restrict__ Wpsl,   // [1024]
                 const float* __restrict__ W1,     // [256,1024]
                 const float* __restrict__ W2,     // [256,256]
                 const float* __restrict__ Wout,   // [256]
                 float* __restrict__ out)          // [2000]
{
    extern __shared__ float smem[];
    float* sB    = smem + OFF_B;
    float* sA    = smem + OFF_A;
    float* h1s   = smem + OFF_H1;
    float* sWpsl = smem + OFF_WPSL;
    float* sWout = smem + OFF_WOUT;
    float* sAtom = smem + OFF_SATOM;

    const int tid    = threadIdx.x;
    const int lane   = tid & 31;
    const int warpId = tid >> 5;
    const int g = lane >> 2;        // group id (row within m16/n8 tile)
    const int t = lane & 3;         // thread-in-group (k/col)
    const int wr = (warpId & 3) * 32;   // warp row base in M tile
    const int wc = (warpId >> 2) * 64;  // warp col base in N=256
    const long tileBase = (long)blockIdx.x * M_TILE;

    const uint32_t sA_base = (uint32_t)__cvta_generic_to_shared(sA);
    const uint32_t sB_base = (uint32_t)__cvta_generic_to_shared(sB);

    // preload small vectors (visible after first __syncthreads in the mainloop)
    for (int i = tid; i < 1024; i += NTHREADS) sWpsl[i] = Wpsl[i];
    if (tid < 256) sWout[tid] = Wout[tid];

    float acc[2][8][4];
#pragma unroll
    for (int mt = 0; mt < 2; mt++)
#pragma unroll
        for (int nt = 0; nt < 8; nt++)
#pragma unroll
            for (int c = 0; c < 4; c++) acc[mt][nt][c] = 0.0f;

    float psl = 0.0f;

    // ---------- GEMM1: [128 x 1024] x W1^T -> acc [128 x 256] ----------
    // chunk loader for GEMM1 (A from ps, B from W1)
    auto load_g1 = [&](int kc, int buf) {
#pragma unroll
        for (int j = 0; j < 2; j++) {               // A: 1024 float4 / 512 thr
            int idx = tid + j * NTHREADS;
            int row = idx >> 3, c4 = idx & 7;
            long arow = tileBase + row;
            int sidx = (buf * 128 + row) * SA_STRIDE + c4 * 4;
            if (arow < N_ATOMS) {
                cp_async16(sA_base + sidx * 4, ps + arow * (long)N_FEAT + kc * KC + c4 * 4);
            } else {
                *(float4*)(sA + sidx) = make_float4(0.f, 0.f, 0.f, 0.f);
            }
        }
#pragma unroll
        for (int j = 0; j < 4; j++) {               // B: 2048 float4 / 512 thr
            int idx = tid + j * NTHREADS;
            int row = idx >> 3, c4 = idx & 7;
            int sidx = (buf * 256 + row) * SB_STRIDE + c4 * 4;
            cp_async16(sB_base + sidx * 4, W1 + row * N_FEAT + kc * KC + c4 * 4);
        }
        cp_commit();
    };

    load_g1(0, 0);

    for (int kc = 0; kc < N_FEAT / KC; kc++) {
        if (kc + 1 < N_FEAT / KC) { load_g1(kc + 1, (kc + 1) & 1); cp_wait1(); }
        else                      { cp_wait0(); }
        __syncthreads();

        const int buf = kc & 1;
        const float* A = sA + buf * 128 * SA_STRIDE;
        const float* B = sB + buf * 256 * SB_STRIDE;

        // psl partial (fp32, from raw A tile): 4 threads per row, 8 k each
        {
            int row = tid >> 2;
            int k0  = (tid & 3) * 8;
            const float* wp = sWpsl + kc * KC + k0;
            const float* ar = A + row * SA_STRIDE + k0;
#pragma unroll
            for (int kk = 0; kk < 8; kk++) psl += ar[kk] * wp[kk];
        }

#pragma unroll
        for (int ks = 0; ks < KC; ks += 8) {
            uint32_t afr[2][4];
#pragma unroll
            for (int mt = 0; mt < 2; mt++) {
                int r = wr + mt * 16;
                afr[mt][0] = cvt_tf32(A[(r + g) * SA_STRIDE + ks + t]);
                afr[mt][1] = cvt_tf32(A[(r + g + 8) * SA_STRIDE + ks + t]);
                afr[mt][2] = cvt_tf32(A[(r + g) * SA_STRIDE + ks + t + 4]);
                afr[mt][3] = cvt_tf32(A[(r + g + 8) * SA_STRIDE + ks + t + 4]);
            }
#pragma unroll
            for (int nt = 0; nt < 8; nt++) {
                int n = wc + nt * 8 + g;
                uint32_t bfr[2];
                bfr[0] = cvt_tf32(B[n * SB_STRIDE + ks + t]);
                bfr[1] = cvt_tf32(B[n * SB_STRIDE + ks + t + 4]);
                mma_tf32(acc[0][nt], afr[0], bfr);
                mma_tf32(acc[1][nt], afr[1], bfr);
            }
        }
        __syncthreads();
    }

    // psl reduce (4 threads per row) -> sAtom[row]
    psl += __shfl_xor_sync(0xffffffffu, psl, 1);
    psl += __shfl_xor_sync(0xffffffffu, psl, 2);
    if ((tid & 3) == 0) sAtom[tid >> 2] = psl;

    // ---------- prefetch W2 chunk 0 while writing h1 ----------
    auto load_g2 = [&](int kc, int buf) {
#pragma unroll
        for (int j = 0; j < 4; j++) {
            int idx = tid + j * NTHREADS;
            int row = idx >> 3, c4 = idx & 7;
            int sidx = (buf * 256 + row) * SB_STRIDE + c4 * 4;
            cp_async16(sB_base + sidx * 4, W2 + row * H1_DIM + kc * KC + c4 * 4);
        }
        cp_commit();
    };
    load_g2(0, 0);

    // h1 = silu(acc), stored fp32 in SMEM (aliases dead A region); reset acc
#pragma unroll
    for (int mt = 0; mt < 2; mt++) {
        int r0 = wr + mt * 16 + g;
#pragma unroll
        for (int nt = 0; nt < 8; nt++) {
            int col = wc + nt * 8 + 2 * t;
            h1s[r0 * H1_STRIDE + col]           = silu(acc[mt][nt][0]);
            h1s[r0 * H1_STRIDE + col + 1]       = silu(acc[mt][nt][1]);
            h1s[(r0 + 8) * H1_STRIDE + col]     = silu(acc[mt][nt][2]);
            h1s[(r0 + 8) * H1_STRIDE + col + 1] = silu(acc[mt][nt][3]);
            acc[mt][nt][0] = acc[mt][nt][1] = acc[mt][nt][2] = acc[mt][nt][3] = 0.0f;
        }
    }
    __syncthreads();

    // ---------- GEMM2: h1[128 x 256] x W2^T -> acc ----------
    for (int kc = 0; kc < H1_DIM / KC; kc++) {
        if (kc + 1 < H1_DIM / KC) { load_g2(kc + 1, (kc + 1) & 1); cp_wait1(); }
        else                      { cp_wait0(); }
        __syncthreads();

        const float* B = sB + (kc & 1) * 256 * SB_STRIDE;
        const int kb = kc * KC;
#pragma unroll
        for (int ks = 0; ks < KC; ks += 8) {
            uint32_t afr[2][4];
#pragma unroll
            for (int mt = 0; mt < 2; mt++) {
                int r = wr + mt * 16;
                afr[mt][0] = cvt_tf32(h1s[(r + g) * H1_STRIDE + kb + ks + t]);
                afr[mt][1] = cvt_tf32(h1s[(r + g + 8) * H1_STRIDE + kb + ks + t]);
                afr[mt][2] = cvt_tf32(h1s[(r + g) * H1_STRIDE + kb + ks + t + 4]);
                afr[mt][3] = cvt_tf32(h1s[(r + g + 8) * H1_STRIDE + kb + ks + t + 4]);
            }
#pragma unroll
            for (int nt = 0; nt < 8; nt++) {
                int n = wc + nt * 8 + g;
                uint32_t bfr[2];
                bfr[0] = cvt_tf32(B[n * SB_STRIDE + ks + t]);
                bfr[1] = cvt_tf32(B[n * SB_STRIDE + ks + t + 4]);
                mma_tf32(acc[0][nt], afr[0], bfr);
                mma_tf32(acc[1][nt], afr[1], bfr);
            }
        }
        __syncthreads();
    }

    // ---------- epilogue: h2 = silu(acc); psnn = h2 . Wout; reduce ----------
#pragma unroll
    for (int mt = 0; mt < 2; mt++) {
        float p0 = 0.0f, p1 = 0.0f;
#pragma unroll
        for (int nt = 0; nt < 8; nt++) {
            int col = wc + nt * 8 + 2 * t;
            float w0 = sWout[col], w1 = sWout[col + 1];
            p0 += silu(acc[mt][nt][0]) * w0 + silu(acc[mt][nt][1]) * w1;
            p1 += silu(acc[mt][nt][2]) * w0 + silu(acc[mt][nt][3]) * w1;
        }
        p0 += __shfl_xor_sync(0xffffffffu, p0, 1);
        p0 += __shfl_xor_sync(0xffffffffu, p0, 2);
        p1 += __shfl_xor_sync(0xffffffffu, p1, 1);
        p1 += __shfl_xor_sync(0xffffffffu, p1, 2);
        if (t == 0) {
            atomicAdd(&sAtom[wr + mt * 16 + g], p0);
            atomicAdd(&sAtom[wr + mt * 16 + 8 + g], p1);
        }
    }
    __syncthreads();

    // final per-atom value -> segment sum via global atomics
    if (tid < M_TILE) {
        long a = tileBase + tid;
        if (a < N_ATOMS) {
            float v = sAtom[tid] + Wcomp[numbers[a]];
            atomicAdd(&out[batch[a]], v);
        }
    }
}

extern "C" void kernel_launch(void* const* d_in, const int* in_sizes, int n_in,
                              void* d_out, int out_size) {
    const float* ps      = (const float*)d_in[0];
    const int*   numbers = (const int*)  d_in[1];
    const int*   batch   = (const int*)  d_in[2];
    const float* Wcomp   = (const float*)d_in[3];
    const float* Wpsl    = (const float*)d_in[4];
    const float* W1      = (const float*)d_in[5];
    const float* W2      = (const float*)d_in[6];
    const float* Wout    = (const float*)d_in[7];
    float* out = (float*)d_out;

    cudaFuncSetAttribute(fused_psm_kernel,
                         cudaFuncAttributeMaxDynamicSharedMemorySize, SMEM_BYTES);

    zero_out_kernel<<<(out_size + 255) / 256, 256>>>(out, out_size);

    int grid = (N_ATOMS + M_TILE - 1) / M_TILE;  // 1563
    fused_psm_kernel<<<grid, NTHREADS, SMEM_BYTES>>>(
        ps, numbers, batch, Wcomp, Wpsl, W1, W2, Wout, out);
}

// round 2
// speedup vs baseline: 1.0004x; 1.0004x over previous
#include <cuda_runtime.h>
#include <cstdint>

#define N_ATOMS  200000
#define N_FEAT   1024
#define H1_DIM   256
#define H2_DIM   256
#define N_STRUCT 2000

#define M_TILE   128
#define NTHREADS 512
#define KC       32     // k-chunk width

#define SA_STRIDE 36    // 32 + 4 pad (floats)
#define SB_STRIDE 36
#define H1_STRIDE 260   // 256 + 4 pad

// shared memory layout (float offsets)
#define OFF_B     0                      // 2*256*36 = 18432
#define OFF_A     (2*256*SB_STRIDE)      // 18432, size 2*128*36 = 9216
#define OFF_H1    OFF_A                  // aliases A (A dead when h1 written), 128*260 = 33280
#define OFF_WPSL  (OFF_A + 128*H1_STRIDE)   // 51712
#define OFF_WOUT  (OFF_WPSL + 1024)         // 52736
#define OFF_SATOM (OFF_WOUT + 256)          // 52992
#define SMEM_FLOATS (OFF_SATOM + 128)       // 53120
#define SMEM_BYTES (SMEM_FLOATS * 4)        // 212480 B

__device__ __forceinline__ uint32_t cvt_tf32(float x) {
    uint32_t r;
    asm("cvt.rna.tf32.f32 %0, %1;" : "=r"(r) : "f"(x));
    return r;
}

__device__ __forceinline__ void mma_tf32(float c[4], const uint32_t a[4], const uint32_t b[2]) {
    asm volatile(
        "mma.sync.aligned.m16n8k8.row.col.f32.tf32.tf32.f32 "
        "{%0,%1,%2,%3}, {%4,%5,%6,%7}, {%8,%9}, {%0,%1,%2,%3};\n"
        : "+f"(c[0]), "+f"(c[1]), "+f"(c[2]), "+f"(c[3])
        : "r"(a[0]), "r"(a[1]), "r"(a[2]), "r"(a[3]), "r"(b[0]), "r"(b[1]));
}

__device__ __forceinline__ void cp_async16(uint32_t saddr, const void* gptr) {
    asm volatile("cp.async.cg.shared.global [%0], [%1], 16;\n" :: "r"(saddr), "l"(gptr));
}
__device__ __forceinline__ void cp_commit() { asm volatile("cp.async.commit_group;\n"); }
__device__ __forceinline__ void cp_wait1()  { asm volatile("cp.async.wait_group 1;\n"); }
__device__ __forceinline__ void cp_wait0()  { asm volatile("cp.async.wait_group 0;\n"); }

__device__ __forceinline__ float silu(float x) { return x / (1.0f + __expf(-x)); }

__global__ void zero_out_kernel(float* out, int n) {
    int i = blockIdx.x * blockDim.x + threadIdx.x;
    if (i < n) out[i] = 0.0f;
}

__global__ void __launch_bounds__(NTHREADS, 1)
fused_psm_kernel(const float* __restrict__ ps,
                 const int*   __restrict__ numbers,
                 const int*   __restrict__ batch,
                 const float* __restrict__ Wcomp,  // [4]
                 const float* __restrict__ Wpsl,   // [1024]
                 const float* __restrict__ W1,     // [256,1024]
                 const float* __restrict__ W2,     // [256,256]
                 const float* __restrict__ Wout,   // [256]
                 float* __restrict__ out)          // [2000]
{
    extern __shared__ float smem[];
    float* sB    = smem + OFF_B;
    float* sA    = smem + OFF_A;
    float* h1s   = smem + OFF_H1;
    float* sWpsl = smem + OFF_WPSL;
    float* sWout = smem + OFF_WOUT;
    float* sAtom = smem + OFF_SATOM;

    const int tid    = threadIdx.x;
    const int lane   = tid & 31;
    const int warpId = tid >> 5;
    const int g = lane >> 2;        // group id (row within m16/n8 tile)
    const int t = lane & 3;         // thread-in-group (k/col)
    const int wr = (warpId & 3) * 32;   // warp row base in M tile
    const int wc = (warpId >> 2) * 64;  // warp col base in N=256
    const long tileBase = (long)blockIdx.x * M_TILE;

    const uint32_t sA_base = (uint32_t)__cvta_generic_to_shared(sA);
    const uint32_t sB_base = (uint32_t)__cvta_generic_to_shared(sB);

    // preload small vectors (visible after first __syncthreads in the mainloop)
    for (int i = tid; i < 1024; i += NTHREADS) sWpsl[i] = Wpsl[i];
    if (tid < 256) sWout[tid] = Wout[tid];

    float acc[2][8][4];
#pragma unroll
    for (int mt = 0; mt < 2; mt++)
#pragma unroll
        for (int nt = 0; nt < 8; nt++)
#pragma unroll
            for (int c = 0; c < 4; c++) acc[mt][nt][c] = 0.0f;

    float psl = 0.0f;

    // ---------- GEMM1: [128 x 1024] x W1^T -> acc [128 x 256] ----------
    // chunk loader for GEMM1 (A from ps, B from W1)
    auto load_g1 = [&](int kc, int buf) {
#pragma unroll
        for (int j = 0; j < 2; j++) {               // A: 1024 float4 / 512 thr
            int idx = tid + j * NTHREADS;
            int row = idx >> 3, c4 = idx & 7;
            long arow = tileBase + row;
            int sidx = (buf * 128 + row) * SA_STRIDE + c4 * 4;
            if (arow < N_ATOMS) {
                cp_async16(sA_base + sidx * 4, ps + arow * (long)N_FEAT + kc * KC + c4 * 4);
            } else {
                *(float4*)(sA + sidx) = make_float4(0.f, 0.f, 0.f, 0.f);
            }
        }
#pragma unroll
        for (int j = 0; j < 4; j++) {               // B: 2048 float4 / 512 thr
            int idx = tid + j * NTHREADS;
            int row = idx >> 3, c4 = idx & 7;
            int sidx = (buf * 256 + row) * SB_STRIDE + c4 * 4;
            cp_async16(sB_base + sidx * 4, W1 + row * N_FEAT + kc * KC + c4 * 4);
        }
        cp_commit();
    };

    load_g1(0, 0);

    for (int kc = 0; kc < N_FEAT / KC; kc++) {
        if (kc + 1 < N_FEAT / KC) { load_g1(kc + 1, (kc + 1) & 1); cp_wait1(); }
        else                      { cp_wait0(); }
        __syncthreads();

        const int buf = kc & 1;
        const float* A = sA + buf * 128 * SA_STRIDE;
        const float* B = sB + buf * 256 * SB_STRIDE;

        // psl partial (fp32, from raw A tile): 4 threads per row, 8 k each
        {
            int row = tid >> 2;
            int k0  = (tid & 3) * 8;
            const float* wp = sWpsl + kc * KC + k0;
            const float* ar = A + row * SA_STRIDE + k0;
#pragma unroll
            for (int kk = 0; kk < 8; kk++) psl += ar[kk] * wp[kk];
        }

#pragma unroll
        for (int ks = 0; ks < KC; ks += 8) {
            uint32_t afr[2][4];
#pragma unroll
            for (int mt = 0; mt < 2; mt++) {
                int r = wr + mt * 16;
                afr[mt][0] = cvt_tf32(A[(r + g) * SA_STRIDE + ks + t]);
                afr[mt][1] = cvt_tf32(A[(r + g + 8) * SA_STRIDE + ks + t]);
                afr[mt][2] = cvt_tf32(A[(r + g) * SA_STRIDE + ks + t + 4]);
                afr[mt][3] = cvt_tf32(A[(r + g + 8) * SA_STRIDE + ks + t + 4]);
            }
#pragma unroll
            for (int nt = 0; nt < 8; nt++) {
                int n = wc + nt * 8 + g;
                uint32_t bfr[2];
                bfr[0] = cvt_tf32(B[n * SB_STRIDE + ks + t]);
                bfr[1] = cvt_tf32(B[n * SB_STRIDE + ks + t + 4]);
                mma_tf32(acc[0][nt], afr[0], bfr);
                mma_tf32(acc[1][nt], afr[1], bfr);
            }
        }
        __syncthreads();
    }

    // psl reduce (4 threads per row) -> sAtom[row]
    psl += __shfl_xor_sync(0xffffffffu, psl, 1);
    psl += __shfl_xor_sync(0xffffffffu, psl, 2);
    if ((tid & 3) == 0) sAtom[tid >> 2] = psl;

    // ---------- prefetch W2 chunk 0 while writing h1 ----------
    auto load_g2 = [&](int kc, int buf) {
#pragma unroll
        for (int j = 0; j < 4; j++) {
            int idx = tid + j * NTHREADS;
            int row = idx >> 3, c4 = idx & 7;
            int sidx = (buf * 256 + row) * SB_STRIDE + c4 * 4;
            cp_async16(sB_base + sidx * 4, W2 + row * H1_DIM + kc * KC + c4 * 4);
        }
        cp_commit();
    };
    load_g2(0, 0);

    // h1 = silu(acc), stored fp32 in SMEM (aliases dead A region); reset acc
#pragma unroll
    for (int mt = 0; mt < 2; mt++) {
        int r0 = wr + mt * 16 + g;
#pragma unroll
        for (int nt = 0; nt < 8; nt++) {
            int col = wc + nt * 8 + 2 * t;
            h1s[r0 * H1_STRIDE + col]           = silu(acc[mt][nt][0]);
            h1s[r0 * H1_STRIDE + col + 1]       = silu(acc[mt][nt][1]);
            h1s[(r0 + 8) * H1_STRIDE + col]     = silu(acc[mt][nt][2]);
            h1s[(r0 + 8) * H1_STRIDE + col + 1] = silu(acc[mt][nt][3]);
            acc[mt][nt][0] = acc[mt][nt][1] = acc[mt][nt][2] = acc[mt][nt][3] = 0.0f;
        }
    }
    __syncthreads();

    // ---------- GEMM2: h1[128 x 256] x W2^T -> acc ----------
    for (int kc = 0; kc < H1_DIM / KC; kc++) {
        if (kc + 1 < H1_DIM / KC) { load_g2(kc + 1, (kc + 1) & 1); cp_wait1(); }
        else                      { cp_wait0(); }
        __syncthreads();

        const float* B = sB + (kc & 1) * 256 * SB_STRIDE;
        const int kb = kc * KC;
#pragma unroll
        for (int ks = 0; ks < KC; ks += 8) {
            uint32_t afr[2][4];
#pragma unroll
            for (int mt = 0; mt < 2; mt++) {
                int r = wr + mt * 16;
                afr[mt][0] = cvt_tf32(h1s[(r + g) * H1_STRIDE + kb + ks + t]);
                afr[mt][1] = cvt_tf32(h1s[(r + g + 8) * H1_STRIDE + kb + ks + t]);
                afr[mt][2] = cvt_tf32(h1s[(r + g) * H1_STRIDE + kb + ks + t + 4]);
                afr[mt][3] = cvt_tf32(h1s[(r + g + 8) * H1_STRIDE + kb + ks + t + 4]);
            }
#pragma unroll
            for (int nt = 0; nt < 8; nt++) {
                int n = wc + nt * 8 + g;
                uint32_t bfr[2];
                bfr[0] = cvt_tf32(B[n * SB_STRIDE + ks + t]);
                bfr[1] = cvt_tf32(B[n * SB_STRIDE + ks + t + 4]);
                mma_tf32(acc[0][nt], afr[0], bfr);
                mma_tf32(acc[1][nt], afr[1], bfr);
            }
        }
        __syncthreads();
    }

    // ---------- epilogue: h2 = silu(acc); psnn = h2 . Wout; reduce ----------
#pragma unroll
    for (int mt = 0; mt < 2; mt++) {
        float p0 = 0.0f, p1 = 0.0f;
#pragma unroll
        for (int nt = 0; nt < 8; nt++) {
            int col = wc + nt * 8 + 2 * t;
            float w0 = sWout[col], w1 = sWout[col + 1];
            p0 += silu(acc[mt][nt][0]) * w0 + silu(acc[mt][nt][1]) * w1;
            p1 += silu(acc[mt][nt][2]) * w0 + silu(acc[mt][nt][3]) * w1;
        }
        p0 += __shfl_xor_sync(0xffffffffu, p0, 1);
        p0 += __shfl_xor_sync(0xffffffffu, p0, 2);
        p1 += __shfl_xor_sync(0xffffffffu, p1, 1);
        p1 += __shfl_xor_sync(0xffffffffu, p1, 2);
        if (t == 0) {
            atomicAdd(&sAtom[wr + mt * 16 + g], p0);
            atomicAdd(&sAtom[wr + mt * 16 + 8 + g], p1);
        }
    }
    __syncthreads();

    // final per-atom value -> segment sum via global atomics
    if (tid < M_TILE) {
        long a = tileBase + tid;
        if (a < N_ATOMS) {
            float v = sAtom[tid] + Wcomp[numbers[a]];
            atomicAdd(&out[batch[a]], v);
        }
    }
}

extern "C" void kernel_launch(void* const* d_in, const int* in_sizes, int n_in,
                              void* d_out, int out_size) {
    const float* ps      = (const float*)d_in[0];
    const int*   numbers = (const int*)  d_in[1];
    const int*   batch   = (const int*)  d_in[2];
    const float* Wcomp   = (const float*)d_in[3];
    const float* Wpsl    = (const float*)d_in[4];
    const float* W1      = (const float*)d_in[5];
    const float* W2      = (const float*)d_in[6];
    const float* Wout    = (const float*)d_in[7];
    float* out = (float*)d_out;

    cudaFuncSetAttribute(fused_psm_kernel,
                         cudaFuncAttributeMaxDynamicSharedMemorySize, SMEM_BYTES);

    zero_out_kernel<<<(out_size + 255) / 256, 256>>>(out, out_size);

    int grid = (N_ATOMS + M_TILE - 1) / M_TILE;  // 1563
    fused_psm_kernel<<<grid, NTHREADS, SMEM_BYTES>>>(
        ps, numbers, batch, Wcomp, Wpsl, W1, W2, Wout, out);
}